// round 2
// baseline (speedup 1.0000x reference)
#include <cuda_runtime.h>
#include <math.h>

#define BSZ 2
#define TSEQ 2048
#define CDIM 1024
#define NHEAD 16
#define HDIM 64
#define EPS 1e-6f

// Scratch (allocation-free rule: __device__ globals)
__device__ float g_qkv[(size_t)BSZ * TSEQ * 3 * CDIM];  // [4096][3072]
__device__ float g_att[(size_t)BSZ * TSEQ * CDIM];      // [4096][1024]

// ---------------------------------------------------------------------------
// GEMM: C[M,N] = A[M,K] @ B[K,N] + bias[N]
// BM=128, BN=128, BK=16, 256 threads, 8x8 per thread
// ---------------------------------------------------------------------------
__global__ __launch_bounds__(256)
void gemm_bias_kernel(const float* __restrict__ A, const float* __restrict__ B,
                      const float* __restrict__ bias, float* __restrict__ C,
                      int M, int N, int K) {
    __shared__ float As[16][132];   // [BK][BM+4]; +4 keeps float4 alignment, breaks conflicts
    __shared__ float Bs[16][128];   // [BK][BN]

    const int t  = threadIdx.x;
    const int tx = t & 15;          // 16 cols of threads
    const int ty = t >> 4;          // 16 rows of threads
    const int m0 = blockIdx.y * 128;
    const int n0 = blockIdx.x * 128;

    float acc[8][8];
#pragma unroll
    for (int i = 0; i < 8; i++)
#pragma unroll
        for (int j = 0; j < 8; j++) acc[i][j] = 0.f;

    for (int k0 = 0; k0 < K; k0 += 16) {
        // Load A tile (128x16) transposed into As[kk][m]
#pragma unroll
        for (int i = 0; i < 2; i++) {
            int idx4 = t + i * 256;            // 0..511 float4s
            int m    = idx4 >> 2;              // 0..127
            int k4   = (idx4 & 3) << 2;        // 0,4,8,12
            float4 v = *(const float4*)&A[(size_t)(m0 + m) * K + k0 + k4];
            As[k4 + 0][m] = v.x;
            As[k4 + 1][m] = v.y;
            As[k4 + 2][m] = v.z;
            As[k4 + 3][m] = v.w;
        }
        // Load B tile (16x128) natural layout
#pragma unroll
        for (int i = 0; i < 2; i++) {
            int idx4 = t + i * 256;            // 0..511
            int n4   = (idx4 & 31) << 2;       // 0..124 step 4
            int kk   = idx4 >> 5;              // 0..15
            *(float4*)&Bs[kk][n4] =
                *(const float4*)&B[(size_t)(k0 + kk) * N + n0 + n4];
        }
        __syncthreads();

#pragma unroll
        for (int kk = 0; kk < 16; kk++) {
            float a[8], b[8];
            *(float4*)&a[0] = *(const float4*)&As[kk][ty * 8];
            *(float4*)&a[4] = *(const float4*)&As[kk][ty * 8 + 4];
            *(float4*)&b[0] = *(const float4*)&Bs[kk][tx * 8];
            *(float4*)&b[4] = *(const float4*)&Bs[kk][tx * 8 + 4];
#pragma unroll
            for (int i = 0; i < 8; i++)
#pragma unroll
                for (int j = 0; j < 8; j++) acc[i][j] += a[i] * b[j];
        }
        __syncthreads();
    }

#pragma unroll
    for (int i = 0; i < 8; i++) {
        int row = m0 + ty * 8 + i;
#pragma unroll
        for (int j = 0; j < 8; j++) {
            int col = n0 + tx * 8 + j;
            C[(size_t)row * N + col] = acc[i][j] + bias[col];
        }
    }
}

// ---------------------------------------------------------------------------
// Yat causal attention, flash-style streaming.
// Grid: (T/64, H, B). 256 threads. Q tile 64 rows, K tile 64 keys, D=64.
// score = dot^2 / (|q|^2 + |k|^2 - 2 dot + eps), causal, online softmax.
// ---------------------------------------------------------------------------
__global__ __launch_bounds__(256)
void yat_attn_kernel(const float* __restrict__ qkv, float* __restrict__ out) {
    extern __shared__ float sm[];
    float* Qs  = sm;                 // [64][68]
    float* Ks  = Qs + 64 * 68;       // [64][68]
    float* Vs  = Ks + 64 * 68;       // [64][68]
    float* S   = Vs + 64 * 68;       // [64][65]
    float* qsq = S + 64 * 65;        // [64]
    float* ksq = qsq + 64;           // [64]

    const int t  = threadIdx.x;
    const int qt = blockIdx.x;       // query tile 0..31
    const int h  = blockIdx.y;
    const int b  = blockIdx.z;
    const int q0 = qt * 64;
    const int qcol = h * HDIM;
    const float* base = qkv + (size_t)b * TSEQ * 3 * CDIM;

    // Load Q tile
#pragma unroll
    for (int i = 0; i < 4; i++) {
        int idx4 = t + i * 256;        // 0..1023 float4s
        int r    = idx4 >> 4;          // 0..63
        int d4   = (idx4 & 15) << 2;   // 0..60
        *(float4*)&Qs[r * 68 + d4] =
            *(const float4*)&base[(size_t)(q0 + r) * (3 * CDIM) + qcol + d4];
    }
    __syncthreads();
    if (t < 64) {
        float s = 0.f;
#pragma unroll
        for (int d = 0; d < 64; d++) { float v = Qs[t * 68 + d]; s += v * v; }
        qsq[t] = s;
    }

    const int tx = t & 15;            // phase-1: 16x16 threads, 4x4 each
    const int ty = t >> 4;
    const int r2 = t & 63;            // phase-2: query row
    const int ds = (t >> 6) * 16;     // phase-2: D slice start

    float m_run = -INFINITY, l_run = 0.f;
    float acc[16];
#pragma unroll
    for (int j = 0; j < 16; j++) acc[j] = 0.f;

    for (int kt = 0; kt <= qt; kt++) {
        const int k0 = kt * 64;
        // Load K, V tiles
#pragma unroll
        for (int i = 0; i < 4; i++) {
            int idx4 = t + i * 256;
            int r    = idx4 >> 4;
            int d4   = (idx4 & 15) << 2;
            const float* row = &base[(size_t)(k0 + r) * (3 * CDIM)];
            *(float4*)&Ks[r * 68 + d4] = *(const float4*)&row[CDIM + qcol + d4];
            *(float4*)&Vs[r * 68 + d4] = *(const float4*)&row[2 * CDIM + qcol + d4];
        }
        __syncthreads();
        if (t < 64) {
            float s = 0.f;
#pragma unroll
            for (int d = 0; d < 64; d++) { float v = Ks[t * 68 + d]; s += v * v; }
            ksq[t] = s;
        }
        __syncthreads();

        // Phase 1: 4x4 score block per thread
        float dot[4][4];
#pragma unroll
        for (int i = 0; i < 4; i++)
#pragma unroll
            for (int j = 0; j < 4; j++) dot[i][j] = 0.f;

#pragma unroll
        for (int dd = 0; dd < 64; dd += 4) {
            float4 qv[4], kv[4];
#pragma unroll
            for (int i = 0; i < 4; i++)
                qv[i] = *(const float4*)&Qs[(ty * 4 + i) * 68 + dd];
#pragma unroll
            for (int j = 0; j < 4; j++)
                kv[j] = *(const float4*)&Ks[(tx * 4 + j) * 68 + dd];
#pragma unroll
            for (int i = 0; i < 4; i++)
#pragma unroll
                for (int j = 0; j < 4; j++) {
                    dot[i][j] += qv[i].x * kv[j].x + qv[i].y * kv[j].y +
                                 qv[i].z * kv[j].z + qv[i].w * kv[j].w;
                }
        }
#pragma unroll
        for (int i = 0; i < 4; i++) {
            int r = ty * 4 + i;
#pragma unroll
            for (int j = 0; j < 4; j++) {
                int k   = tx * 4 + j;
                float d0  = dot[i][j];
                float den = qsq[r] + ksq[k] - 2.f * d0 + EPS;
                float s   = d0 * d0 / den;
                if (k0 + k > q0 + r) s = -INFINITY;
                S[r * 65 + k] = s;
            }
        }
        __syncthreads();

        // Phase 2: online softmax + PV accumulation (thread owns (r2, ds..ds+15))
        float tmax = -INFINITY;
#pragma unroll
        for (int k = 0; k < 64; k++) tmax = fmaxf(tmax, S[r2 * 65 + k]);
        float m_new = fmaxf(m_run, tmax);
        float scale = __expf(m_run - m_new);   // 0 when m_run == -inf
        l_run *= scale;
#pragma unroll
        for (int j = 0; j < 16; j++) acc[j] *= scale;

#pragma unroll 4
        for (int k = 0; k < 64; k++) {
            float p = __expf(S[r2 * 65 + k] - m_new);
            l_run += p;
            float4 v0 = *(const float4*)&Vs[k * 68 + ds + 0];
            float4 v1 = *(const float4*)&Vs[k * 68 + ds + 4];
            float4 v2 = *(const float4*)&Vs[k * 68 + ds + 8];
            float4 v3 = *(const float4*)&Vs[k * 68 + ds + 12];
            acc[0]  += p * v0.x; acc[1]  += p * v0.y; acc[2]  += p * v0.z; acc[3]  += p * v0.w;
            acc[4]  += p * v1.x; acc[5]  += p * v1.y; acc[6]  += p * v1.z; acc[7]  += p * v1.w;
            acc[8]  += p * v2.x; acc[9]  += p * v2.y; acc[10] += p * v2.z; acc[11] += p * v2.w;
            acc[12] += p * v3.x; acc[13] += p * v3.y; acc[14] += p * v3.z; acc[15] += p * v3.w;
        }
        m_run = m_new;
        __syncthreads();
    }

    const float inv = 1.f / l_run;
    float* orow = out + ((size_t)(b * TSEQ + q0 + r2)) * CDIM + h * HDIM + ds;
#pragma unroll
    for (int j = 0; j < 16; j++) orow[j] = acc[j] * inv;
}

// ---------------------------------------------------------------------------
// Launch
// ---------------------------------------------------------------------------
extern "C" void kernel_launch(void* const* d_in, const int* in_sizes, int n_in,
                              void* d_out, int out_size) {
    const float* x     = (const float*)d_in[0];   // [2,2048,1024]
    const float* w_qkv = (const float*)d_in[1];   // [1024,3072]
    const float* b_qkv = (const float*)d_in[2];   // [3072]
    const float* w_out = (const float*)d_in[3];   // [1024,1024]
    const float* b_out = (const float*)d_in[4];   // [1024]
    float* out = (float*)d_out;                   // [2,2048,1024]

    void* p_qkv = nullptr;
    void* p_att = nullptr;
    cudaGetSymbolAddress(&p_qkv, g_qkv);
    cudaGetSymbolAddress(&p_att, g_att);
    float* qkv = (float*)p_qkv;
    float* att = (float*)p_att;

    const int M = BSZ * TSEQ;     // 4096
    const int K = CDIM;           // 1024
    const int N1 = 3 * CDIM;      // 3072
    const int N2 = CDIM;          // 1024

    // 1) QKV projection
    {
        dim3 grid(N1 / 128, M / 128);
        gemm_bias_kernel<<<grid, 256>>>(x, w_qkv, b_qkv, qkv, M, N1, K);
    }

    // 2) Yat causal attention
    {
        const int smem_bytes = (3 * 64 * 68 + 64 * 65 + 128) * (int)sizeof(float);  // 69376
        cudaFuncSetAttribute(yat_attn_kernel,
                             cudaFuncAttributeMaxDynamicSharedMemorySize, smem_bytes);
        dim3 grid(TSEQ / 64, NHEAD, BSZ);
        yat_attn_kernel<<<grid, 256, smem_bytes>>>(qkv, att);
    }

    // 3) Output projection
    {
        dim3 grid(N2 / 128, M / 128);
        gemm_bias_kernel<<<grid, 256>>>(att, w_out, b_out, out, M, N2, K);
    }
}

// round 4
// speedup vs baseline: 1.3001x; 1.3001x over previous
#include <cuda_runtime.h>
#include <cuda_bf16.h>
#include <math.h>
#include <stdint.h>

#define BSZ 2
#define TSEQ 2048
#define CDIM 1024
#define NHEAD 16
#define HDIM 64
#define EPS 1e-6f

#define MTOT (BSZ * TSEQ)          // 4096
#define N1 (3 * CDIM)              // 3072
#define KD CDIM                    // 1024 (K for both GEMMs)

// ---------------------------------------------------------------------------
// Scratch (__device__ globals; no allocation allowed)
// ---------------------------------------------------------------------------
__device__ float g_qkv[(size_t)MTOT * N1];              // 48 MB fp32
__device__ float g_att[(size_t)MTOT * CDIM];            // 16 MB fp32
__device__ __nv_bfloat16 g_xhi[(size_t)MTOT * KD];
__device__ __nv_bfloat16 g_xlo[(size_t)MTOT * KD];
__device__ __nv_bfloat16 g_wqkvT_hi[(size_t)N1 * KD];   // [N][K]
__device__ __nv_bfloat16 g_wqkvT_lo[(size_t)N1 * KD];
__device__ __nv_bfloat16 g_woT_hi[(size_t)CDIM * KD];   // [N][K]
__device__ __nv_bfloat16 g_woT_lo[(size_t)CDIM * KD];
__device__ __nv_bfloat16 g_atthi[(size_t)MTOT * KD];
__device__ __nv_bfloat16 g_attlo[(size_t)MTOT * KD];

// ---------------------------------------------------------------------------
// PTX helpers: cp.async / ldmatrix / mma.sync (all baseline sm_80+, no 'a' feats)
// ---------------------------------------------------------------------------
__device__ __forceinline__ uint32_t smem_u32(const void* p) {
    uint32_t a;
    asm("{ .reg .u64 t; cvta.to.shared.u64 t, %1; cvt.u32.u64 %0, t; }"
        : "=r"(a) : "l"(p));
    return a;
}

#define CP16(dst, src) \
    asm volatile("cp.async.cg.shared.global [%0], [%1], 16;" \
                 :: "r"(dst), "l"(src))
#define CP_COMMIT() asm volatile("cp.async.commit_group;" ::: "memory")
#define CP_WAIT(n)  asm volatile("cp.async.wait_group %0;" :: "n"(n) : "memory")

__device__ __forceinline__ void ldsm_x4(uint32_t* r, uint32_t addr) {
    asm volatile("ldmatrix.sync.aligned.m8n8.x4.shared.b16 {%0,%1,%2,%3}, [%4];"
                 : "=r"(r[0]), "=r"(r[1]), "=r"(r[2]), "=r"(r[3]) : "r"(addr));
}

__device__ __forceinline__ void mma16816(float* c, const uint32_t* a, const uint32_t* b) {
    asm volatile(
        "mma.sync.aligned.m16n8k16.row.col.f32.bf16.bf16.f32 "
        "{%0,%1,%2,%3}, {%4,%5,%6,%7}, {%8,%9}, {%0,%1,%2,%3};"
        : "+f"(c[0]), "+f"(c[1]), "+f"(c[2]), "+f"(c[3])
        : "r"(a[0]), "r"(a[1]), "r"(a[2]), "r"(a[3]), "r"(b[0]), "r"(b[1]));
}

// ---------------------------------------------------------------------------
// Pre-pass: split fp32 -> bf16 hi/lo (elementwise)
// ---------------------------------------------------------------------------
__global__ void split_kernel(const float* __restrict__ src,
                             __nv_bfloat16* __restrict__ hi,
                             __nv_bfloat16* __restrict__ lo, int n4) {
    int i = blockIdx.x * blockDim.x + threadIdx.x;
    if (i >= n4) return;
    float4 v = ((const float4*)src)[i];
    float a[4] = {v.x, v.y, v.z, v.w};
    ushort4 hv, lv;
    unsigned short* hp = &hv.x;
    unsigned short* lp = &lv.x;
#pragma unroll
    for (int j = 0; j < 4; j++) {
        __nv_bfloat16 h = __float2bfloat16(a[j]);
        float r = a[j] - __bfloat162float(h);
        __nv_bfloat16 l = __float2bfloat16(r);
        hp[j] = *(unsigned short*)&h;
        lp[j] = *(unsigned short*)&l;
    }
    ((ushort4*)hi)[i] = hv;
    ((ushort4*)lo)[i] = lv;
}

// ---------------------------------------------------------------------------
// Pre-pass: transpose + split  W[K,N] fp32 -> Wt_hi/lo[N,K] bf16
// ---------------------------------------------------------------------------
__global__ __launch_bounds__(256)
void transpose_split_kernel(const float* __restrict__ W,
                            __nv_bfloat16* __restrict__ hi,
                            __nv_bfloat16* __restrict__ lo, int K, int N) {
    __shared__ float tile[32][33];
    int n0 = blockIdx.x * 32, k0 = blockIdx.y * 32;
    int tx = threadIdx.x & 31, ty = threadIdx.x >> 5;  // 32 x 8
#pragma unroll
    for (int j = 0; j < 32; j += 8)
        tile[ty + j][tx] = W[(size_t)(k0 + ty + j) * N + n0 + tx];
    __syncthreads();
#pragma unroll
    for (int j = 0; j < 32; j += 8) {
        float v = tile[tx][ty + j];
        __nv_bfloat16 h = __float2bfloat16(v);
        float r = v - __bfloat162float(h);
        hi[(size_t)(n0 + ty + j) * K + k0 + tx] = h;
        lo[(size_t)(n0 + ty + j) * K + k0 + tx] = __float2bfloat16(r);
    }
}

// ---------------------------------------------------------------------------
// HMMA GEMM: C[M,N] = (Ah+Al)[M,K] @ (Bh+Bl)[N,K]^T + bias  (fp32 out)
// CTA 128x128, BK=32, 2-stage cp.async pipeline, K fixed = 1024.
// Smem tiles: 128 rows x 64B data, padded to ROWB=80B (conflict-free ldmatrix).
// Stage layout: Ah +0, Al +TILEB, Bh +2*TILEB, Bl +3*TILEB.
// ---------------------------------------------------------------------------
#define ROWB 80
#define TILEB (128 * ROWB)          // 10240
#define STAGEB (4 * TILEB)          // 40960
#define GEMM_SMEM (2 * STAGEB)      // 81920
#define NKT (KD / 32)               // 32 k-tiles

__device__ __forceinline__ void g2s_stage(uint32_t sdst,
                                          const __nv_bfloat16* Ah, const __nv_bfloat16* Al,
                                          const __nv_bfloat16* Bh, const __nv_bfloat16* Bl,
                                          int m0, int n0, int k0, int t) {
#pragma unroll
    for (int i = 0; i < 2; i++) {
        int idx = t + i * 256;               // 0..511
        int r = idx >> 2;                    // 0..127
        int c = idx & 3;                     // 16B chunk within 64B row
        uint32_t soff = (uint32_t)(r * ROWB + c * 16);
        size_t ga = (size_t)(m0 + r) * KD + k0 + c * 8;
        size_t gb = (size_t)(n0 + r) * KD + k0 + c * 8;
        CP16(sdst + soff,             (const char*)(Ah + ga));
        CP16(sdst + TILEB + soff,     (const char*)(Al + ga));
        CP16(sdst + 2 * TILEB + soff, (const char*)(Bh + gb));
        CP16(sdst + 3 * TILEB + soff, (const char*)(Bl + gb));
    }
}

__global__ __launch_bounds__(256)
void mma_gemm_kernel(const __nv_bfloat16* __restrict__ Ah,
                     const __nv_bfloat16* __restrict__ Al,
                     const __nv_bfloat16* __restrict__ Bh,
                     const __nv_bfloat16* __restrict__ Bl,
                     const float* __restrict__ bias,
                     float* __restrict__ C, int N) {
    extern __shared__ char smem[];
    const uint32_t sb = smem_u32(smem);

    const int t    = threadIdx.x;
    const int lane = t & 31;
    const int w    = t >> 5;          // 8 warps
    const int wm   = w & 1;           // 2 warps along M (64 each)
    const int wn   = w >> 1;          // 4 warps along N (32 each)
    const int m0   = blockIdx.y * 128;
    const int n0   = blockIdx.x * 128;

    float acc[4][4][4];
#pragma unroll
    for (int mi = 0; mi < 4; mi++)
#pragma unroll
        for (int ni = 0; ni < 4; ni++)
#pragma unroll
            for (int r = 0; r < 4; r++) acc[mi][ni][r] = 0.f;

    // prologue: stages 0, 1
    g2s_stage(sb,          Ah, Al, Bh, Bl, m0, n0, 0,  t); CP_COMMIT();
    g2s_stage(sb + STAGEB, Ah, Al, Bh, Bl, m0, n0, 32, t); CP_COMMIT();

    for (int kt = 0; kt < NKT; kt++) {
        if (kt < NKT - 1) { CP_WAIT(1); } else { CP_WAIT(0); }
        __syncthreads();

        const uint32_t st = sb + (uint32_t)(kt & 1) * STAGEB;
#pragma unroll
        for (int ks = 0; ks < 2; ks++) {
            uint32_t ah[4][4], al[4][4];
#pragma unroll
            for (int mi = 0; mi < 4; mi++) {
                uint32_t ra = st + (uint32_t)((wm * 64 + mi * 16 + (lane & 15)) * ROWB
                                              + ks * 32 + (lane >> 4) * 16);
                ldsm_x4(ah[mi], ra);
                ldsm_x4(al[mi], ra + TILEB);
            }
            uint32_t bh[4][2], bl[4][2];
#pragma unroll
            for (int nb = 0; nb < 2; nb++) {
                int g = lane >> 3;
                uint32_t rb = st + 2 * TILEB
                            + (uint32_t)((wn * 32 + nb * 16 + (g >> 1) * 8 + (lane & 7)) * ROWB
                                         + ks * 32 + (g & 1) * 16);
                ldsm_x4(&bh[2 * nb][0], rb);
                ldsm_x4(&bl[2 * nb][0], rb + TILEB);
            }
#pragma unroll
            for (int mi = 0; mi < 4; mi++)
#pragma unroll
                for (int ni = 0; ni < 4; ni++) {
                    mma16816(acc[mi][ni], ah[mi], bh[ni]);
                    mma16816(acc[mi][ni], ah[mi], bl[ni]);
                    mma16816(acc[mi][ni], al[mi], bh[ni]);
                }
        }
        __syncthreads();
        if (kt + 2 < NKT) {
            g2s_stage(sb + (uint32_t)(kt & 1) * STAGEB, Ah, Al, Bh, Bl,
                      m0, n0, (kt + 2) * 32, t);
            CP_COMMIT();
        }
    }

    // epilogue: fragment-direct stores + bias
#pragma unroll
    for (int mi = 0; mi < 4; mi++) {
        int row = m0 + wm * 64 + mi * 16 + (lane >> 2);
#pragma unroll
        for (int ni = 0; ni < 4; ni++) {
            int col = n0 + wn * 32 + ni * 8 + (lane & 3) * 2;
            float b0 = bias[col], b1 = bias[col + 1];
            float2 v0 = {acc[mi][ni][0] + b0, acc[mi][ni][1] + b1};
            float2 v1 = {acc[mi][ni][2] + b0, acc[mi][ni][3] + b1};
            *(float2*)&C[(size_t)row * N + col]       = v0;
            *(float2*)&C[(size_t)(row + 8) * N + col] = v1;
        }
    }
}

// ---------------------------------------------------------------------------
// Yat causal attention (round-1 version — known good)
// ---------------------------------------------------------------------------
__global__ __launch_bounds__(256)
void yat_attn_kernel(const float* __restrict__ qkv, float* __restrict__ out) {
    extern __shared__ float sm[];
    float* Qs  = sm;                 // [64][68]
    float* Ks  = Qs + 64 * 68;       // [64][68]
    float* Vs  = Ks + 64 * 68;       // [64][68]
    float* S   = Vs + 64 * 68;       // [64][65]
    float* qsq = S + 64 * 65;        // [64]
    float* ksq = qsq + 64;           // [64]

    const int t  = threadIdx.x;
    const int qt = blockIdx.x;
    const int h  = blockIdx.y;
    const int b  = blockIdx.z;
    const int q0 = qt * 64;
    const int qcol = h * HDIM;
    const float* base = qkv + (size_t)b * TSEQ * 3 * CDIM;

#pragma unroll
    for (int i = 0; i < 4; i++) {
        int idx4 = t + i * 256;
        int r    = idx4 >> 4;
        int d4   = (idx4 & 15) << 2;
        *(float4*)&Qs[r * 68 + d4] =
            *(const float4*)&base[(size_t)(q0 + r) * (3 * CDIM) + qcol + d4];
    }
    __syncthreads();
    if (t < 64) {
        float s = 0.f;
#pragma unroll
        for (int d = 0; d < 64; d++) { float v = Qs[t * 68 + d]; s += v * v; }
        qsq[t] = s;
    }

    const int tx = t & 15;
    const int ty = t >> 4;
    const int r2 = t & 63;
    const int ds = (t >> 6) * 16;

    float m_run = -INFINITY, l_run = 0.f;
    float acc[16];
#pragma unroll
    for (int j = 0; j < 16; j++) acc[j] = 0.f;

    for (int kt = 0; kt <= qt; kt++) {
        const int k0 = kt * 64;
#pragma unroll
        for (int i = 0; i < 4; i++) {
            int idx4 = t + i * 256;
            int r    = idx4 >> 4;
            int d4   = (idx4 & 15) << 2;
            const float* row = &base[(size_t)(k0 + r) * (3 * CDIM)];
            *(float4*)&Ks[r * 68 + d4] = *(const float4*)&row[CDIM + qcol + d4];
            *(float4*)&Vs[r * 68 + d4] = *(const float4*)&row[2 * CDIM + qcol + d4];
        }
        __syncthreads();
        if (t < 64) {
            float s = 0.f;
#pragma unroll
            for (int d = 0; d < 64; d++) { float v = Ks[t * 68 + d]; s += v * v; }
            ksq[t] = s;
        }
        __syncthreads();

        float dot[4][4];
#pragma unroll
        for (int i = 0; i < 4; i++)
#pragma unroll
            for (int j = 0; j < 4; j++) dot[i][j] = 0.f;

#pragma unroll
        for (int dd = 0; dd < 64; dd += 4) {
            float4 qv[4], kv[4];
#pragma unroll
            for (int i = 0; i < 4; i++)
                qv[i] = *(const float4*)&Qs[(ty * 4 + i) * 68 + dd];
#pragma unroll
            for (int j = 0; j < 4; j++)
                kv[j] = *(const float4*)&Ks[(tx * 4 + j) * 68 + dd];
#pragma unroll
            for (int i = 0; i < 4; i++)
#pragma unroll
                for (int j = 0; j < 4; j++) {
                    dot[i][j] += qv[i].x * kv[j].x + qv[i].y * kv[j].y +
                                 qv[i].z * kv[j].z + qv[i].w * kv[j].w;
                }
        }
#pragma unroll
        for (int i = 0; i < 4; i++) {
            int r = ty * 4 + i;
#pragma unroll
            for (int j = 0; j < 4; j++) {
                int k   = tx * 4 + j;
                float d0  = dot[i][j];
                float den = qsq[r] + ksq[k] - 2.f * d0 + EPS;
                float s   = d0 * d0 / den;
                if (k0 + k > q0 + r) s = -INFINITY;
                S[r * 65 + k] = s;
            }
        }
        __syncthreads();

        float tmax = -INFINITY;
#pragma unroll
        for (int k = 0; k < 64; k++) tmax = fmaxf(tmax, S[r2 * 65 + k]);
        float m_new = fmaxf(m_run, tmax);
        float scale = __expf(m_run - m_new);
        l_run *= scale;
#pragma unroll
        for (int j = 0; j < 16; j++) acc[j] *= scale;

#pragma unroll 4
        for (int k = 0; k < 64; k++) {
            float p = __expf(S[r2 * 65 + k] - m_new);
            l_run += p;
            float4 v0 = *(const float4*)&Vs[k * 68 + ds + 0];
            float4 v1 = *(const float4*)&Vs[k * 68 + ds + 4];
            float4 v2 = *(const float4*)&Vs[k * 68 + ds + 8];
            float4 v3 = *(const float4*)&Vs[k * 68 + ds + 12];
            acc[0]  += p * v0.x; acc[1]  += p * v0.y; acc[2]  += p * v0.z; acc[3]  += p * v0.w;
            acc[4]  += p * v1.x; acc[5]  += p * v1.y; acc[6]  += p * v1.z; acc[7]  += p * v1.w;
            acc[8]  += p * v2.x; acc[9]  += p * v2.y; acc[10] += p * v2.z; acc[11] += p * v2.w;
            acc[12] += p * v3.x; acc[13] += p * v3.y; acc[14] += p * v3.z; acc[15] += p * v3.w;
        }
        m_run = m_new;
        __syncthreads();
    }

    const float inv = 1.f / l_run;
    float* orow = out + ((size_t)(b * TSEQ + q0 + r2)) * CDIM + h * HDIM + ds;
#pragma unroll
    for (int j = 0; j < 16; j++) orow[j] = acc[j] * inv;
}

// ---------------------------------------------------------------------------
// Launch
// ---------------------------------------------------------------------------
extern "C" void kernel_launch(void* const* d_in, const int* in_sizes, int n_in,
                              void* d_out, int out_size) {
    const float* x     = (const float*)d_in[0];
    const float* w_qkv = (const float*)d_in[1];
    const float* b_qkv = (const float*)d_in[2];
    const float* w_out = (const float*)d_in[3];
    const float* b_out = (const float*)d_in[4];
    float* out = (float*)d_out;

    void *p_qkv, *p_att, *p_xhi, *p_xlo, *p_wqh, *p_wql, *p_woh, *p_wol, *p_ahi, *p_alo;
    cudaGetSymbolAddress(&p_qkv, g_qkv);
    cudaGetSymbolAddress(&p_att, g_att);
    cudaGetSymbolAddress(&p_xhi, g_xhi);
    cudaGetSymbolAddress(&p_xlo, g_xlo);
    cudaGetSymbolAddress(&p_wqh, g_wqkvT_hi);
    cudaGetSymbolAddress(&p_wql, g_wqkvT_lo);
    cudaGetSymbolAddress(&p_woh, g_woT_hi);
    cudaGetSymbolAddress(&p_wol, g_woT_lo);
    cudaGetSymbolAddress(&p_ahi, g_atthi);
    cudaGetSymbolAddress(&p_alo, g_attlo);

    static bool attr_done = false;
    if (!attr_done) {
        cudaFuncSetAttribute(mma_gemm_kernel,
                             cudaFuncAttributeMaxDynamicSharedMemorySize, GEMM_SMEM);
        const int attn_smem = (3 * 64 * 68 + 64 * 65 + 128) * (int)sizeof(float);
        cudaFuncSetAttribute(yat_attn_kernel,
                             cudaFuncAttributeMaxDynamicSharedMemorySize, attn_smem);
        attr_done = true;
    }

    // 0) split x, transpose+split weights
    {
        int n4 = MTOT * KD / 4;
        split_kernel<<<(n4 + 255) / 256, 256>>>(x, (__nv_bfloat16*)p_xhi,
                                                (__nv_bfloat16*)p_xlo, n4);
        dim3 g1(N1 / 32, KD / 32);
        transpose_split_kernel<<<g1, 256>>>(w_qkv, (__nv_bfloat16*)p_wqh,
                                            (__nv_bfloat16*)p_wql, KD, N1);
        dim3 g2(CDIM / 32, KD / 32);
        transpose_split_kernel<<<g2, 256>>>(w_out, (__nv_bfloat16*)p_woh,
                                            (__nv_bfloat16*)p_wol, KD, CDIM);
    }

    // 1) QKV projection (HMMA tensor cores)
    {
        dim3 grid(N1 / 128, MTOT / 128);
        mma_gemm_kernel<<<grid, 256, GEMM_SMEM>>>(
            (const __nv_bfloat16*)p_xhi, (const __nv_bfloat16*)p_xlo,
            (const __nv_bfloat16*)p_wqh, (const __nv_bfloat16*)p_wql,
            b_qkv, (float*)p_qkv, N1);
    }

    // 2) Yat causal attention
    {
        const int attn_smem = (3 * 64 * 68 + 64 * 65 + 128) * (int)sizeof(float);
        dim3 grid(TSEQ / 64, NHEAD, BSZ);
        yat_attn_kernel<<<grid, 256, attn_smem>>>((const float*)p_qkv, (float*)p_att);
    }

    // 3) split attention output, output projection (HMMA tensor cores)
    {
        int n4 = MTOT * CDIM / 4;
        split_kernel<<<(n4 + 255) / 256, 256>>>((const float*)p_att,
                                                (__nv_bfloat16*)p_ahi,
                                                (__nv_bfloat16*)p_alo, n4);
        dim3 grid(CDIM / 128, MTOT / 128);
        mma_gemm_kernel<<<grid, 256, GEMM_SMEM>>>(
            (const __nv_bfloat16*)p_ahi, (const __nv_bfloat16*)p_alo,
            (const __nv_bfloat16*)p_woh, (const __nv_bfloat16*)p_wol,
            b_out, out, CDIM);
    }
}

// round 7
// speedup vs baseline: 3.2623x; 2.5092x over previous
#include <cuda_runtime.h>
#include <cuda_bf16.h>
#include <math.h>
#include <stdint.h>

#define BSZ 2
#define TSEQ 2048
#define CDIM 1024
#define NHEAD 16
#define HDIM 64
#define EPS 1e-6f
#define LOG2E 1.4426950408889634f

#define MTOT (BSZ * TSEQ)          // 4096
#define N1 (3 * CDIM)              // 3072
#define KD CDIM                    // 1024

// ---------------------------------------------------------------------------
// Scratch (__device__ globals; no allocation allowed)
// ---------------------------------------------------------------------------
__device__ float g_qkv[(size_t)MTOT * N1];
__device__ float g_att[(size_t)MTOT * CDIM];
__device__ __nv_bfloat16 g_xhi[(size_t)MTOT * KD];
__device__ __nv_bfloat16 g_xlo[(size_t)MTOT * KD];
__device__ __nv_bfloat16 g_wqkvT_hi[(size_t)N1 * KD];
__device__ __nv_bfloat16 g_wqkvT_lo[(size_t)N1 * KD];
__device__ __nv_bfloat16 g_woT_hi[(size_t)CDIM * KD];
__device__ __nv_bfloat16 g_woT_lo[(size_t)CDIM * KD];
__device__ __nv_bfloat16 g_atthi[(size_t)MTOT * KD];
__device__ __nv_bfloat16 g_attlo[(size_t)MTOT * KD];

// attention operands: [b*H+h][t][64] bf16 hi/lo + row sq-norms
#define BHT ((size_t)BSZ * NHEAD * TSEQ)
__device__ __nv_bfloat16 g_qhi[BHT * HDIM];
__device__ __nv_bfloat16 g_qlo[BHT * HDIM];
__device__ __nv_bfloat16 g_khi[BHT * HDIM];
__device__ __nv_bfloat16 g_klo[BHT * HDIM];
__device__ __nv_bfloat16 g_vhi[BHT * HDIM];
__device__ __nv_bfloat16 g_vlo[BHT * HDIM];
__device__ float g_qsq[BHT];
__device__ float g_ksq[BHT];

// ---------------------------------------------------------------------------
// PTX helpers (baseline sm_80+ instructions only — compute_103-safe)
// ---------------------------------------------------------------------------
__device__ __forceinline__ uint32_t smem_u32(const void* p) {
    uint32_t a;
    asm("{ .reg .u64 t; cvta.to.shared.u64 t, %1; cvt.u32.u64 %0, t; }"
        : "=r"(a) : "l"(p));
    return a;
}

#define CP16(dst, src) \
    asm volatile("cp.async.cg.shared.global [%0], [%1], 16;" \
                 :: "r"(dst), "l"(src))
#define CP_COMMIT() asm volatile("cp.async.commit_group;" ::: "memory")
#define CP_WAIT(n)  asm volatile("cp.async.wait_group %0;" :: "n"(n) : "memory")

__device__ __forceinline__ void ldsm_x4(uint32_t* r, uint32_t addr) {
    asm volatile("ldmatrix.sync.aligned.m8n8.x4.shared.b16 {%0,%1,%2,%3}, [%4];"
                 : "=r"(r[0]), "=r"(r[1]), "=r"(r[2]), "=r"(r[3]) : "r"(addr));
}
__device__ __forceinline__ void ldsm_x4t(uint32_t* r, uint32_t addr) {
    asm volatile("ldmatrix.sync.aligned.m8n8.x4.trans.shared.b16 {%0,%1,%2,%3}, [%4];"
                 : "=r"(r[0]), "=r"(r[1]), "=r"(r[2]), "=r"(r[3]) : "r"(addr));
}

__device__ __forceinline__ void mma16816(float* c, const uint32_t* a, const uint32_t* b) {
    asm volatile(
        "mma.sync.aligned.m16n8k16.row.col.f32.bf16.bf16.f32 "
        "{%0,%1,%2,%3}, {%4,%5,%6,%7}, {%8,%9}, {%0,%1,%2,%3};"
        : "+f"(c[0]), "+f"(c[1]), "+f"(c[2]), "+f"(c[3])
        : "r"(a[0]), "r"(a[1]), "r"(a[2]), "r"(a[3]), "r"(b[0]), "r"(b[1]));
}

__device__ __forceinline__ uint32_t pack_bf16x2(float hi, float lo) {
    uint32_t r;
    asm("cvt.rn.bf16x2.f32 %0, %1, %2;" : "=r"(r) : "f"(hi), "f"(lo));
    return r;
}

// exp2 on FMA pipe: magic-constant round + deg-5 poly on [-0.5, 0.5]
__device__ __forceinline__ float exp2_fast(float x) {
    x = fmaxf(x, -126.f);
    float t = x + 12582912.f;                   // round-to-nearest int
    int   i = __float_as_int(t) - 0x4B400000;
    float f = x - (t - 12582912.f);             // f in [-0.5, 0.5]
    float p =            1.33336498e-3f;
    p = fmaf(p, f, 9.61793571e-3f);
    p = fmaf(p, f, 5.55041087e-2f);
    p = fmaf(p, f, 2.40226507e-1f);
    p = fmaf(p, f, 6.93147182e-1f);
    p = fmaf(p, f, 1.0f);
    return __int_as_float(__float_as_int(p) + (i << 23));
}

// rcp on FMA pipe: bit trick + 3 Newton iterations (d > 0)
__device__ __forceinline__ float rcp_fast(float d) {
    float y = __int_as_float(0x7EF311C3 - __float_as_int(d));
    y = y * fmaf(-d, y, 2.0f);
    y = y * fmaf(-d, y, 2.0f);
    y = y * fmaf(-d, y, 2.0f);
    return y;
}

// ---------------------------------------------------------------------------
// Pre-pass: split fp32 -> bf16 hi/lo (elementwise)
// ---------------------------------------------------------------------------
__global__ void split_kernel(const float* __restrict__ src,
                             __nv_bfloat16* __restrict__ hi,
                             __nv_bfloat16* __restrict__ lo, int n4) {
    int i = blockIdx.x * blockDim.x + threadIdx.x;
    if (i >= n4) return;
    float4 v = ((const float4*)src)[i];
    float a[4] = {v.x, v.y, v.z, v.w};
    ushort4 hv, lv;
    unsigned short* hp = &hv.x;
    unsigned short* lp = &lv.x;
#pragma unroll
    for (int j = 0; j < 4; j++) {
        __nv_bfloat16 h = __float2bfloat16(a[j]);
        float r = a[j] - __bfloat162float(h);
        __nv_bfloat16 l = __float2bfloat16(r);
        hp[j] = *(unsigned short*)&h;
        lp[j] = *(unsigned short*)&l;
    }
    ((ushort4*)hi)[i] = hv;
    ((ushort4*)lo)[i] = lv;
}

// ---------------------------------------------------------------------------
// Pre-pass: transpose + split  W[K,N] fp32 -> Wt_hi/lo[N,K] bf16
// ---------------------------------------------------------------------------
__global__ __launch_bounds__(256)
void transpose_split_kernel(const float* __restrict__ W,
                            __nv_bfloat16* __restrict__ hi,
                            __nv_bfloat16* __restrict__ lo, int K, int N) {
    __shared__ float tile[32][33];
    int n0 = blockIdx.x * 32, k0 = blockIdx.y * 32;
    int tx = threadIdx.x & 31, ty = threadIdx.x >> 5;
#pragma unroll
    for (int j = 0; j < 32; j += 8)
        tile[ty + j][tx] = W[(size_t)(k0 + ty + j) * N + n0 + tx];
    __syncthreads();
#pragma unroll
    for (int j = 0; j < 32; j += 8) {
        float v = tile[tx][ty + j];
        __nv_bfloat16 h = __float2bfloat16(v);
        float r = v - __bfloat162float(h);
        hi[(size_t)(n0 + ty + j) * K + k0 + tx] = h;
        lo[(size_t)(n0 + ty + j) * K + k0 + tx] = __float2bfloat16(r);
    }
}

// ---------------------------------------------------------------------------
// HMMA GEMM (round-4, validated): C = (Ah+Al)(Bh+Bl)^T + bias
// ---------------------------------------------------------------------------
#define ROWB 80
#define TILEB (128 * ROWB)
#define STAGEB (4 * TILEB)
#define GEMM_SMEM (2 * STAGEB)
#define NKT (KD / 32)

__device__ __forceinline__ void g2s_stage(uint32_t sdst,
                                          const __nv_bfloat16* Ah, const __nv_bfloat16* Al,
                                          const __nv_bfloat16* Bh, const __nv_bfloat16* Bl,
                                          int m0, int n0, int k0, int t) {
#pragma unroll
    for (int i = 0; i < 2; i++) {
        int idx = t + i * 256;
        int r = idx >> 2;
        int c = idx & 3;
        uint32_t soff = (uint32_t)(r * ROWB + c * 16);
        size_t ga = (size_t)(m0 + r) * KD + k0 + c * 8;
        size_t gb = (size_t)(n0 + r) * KD + k0 + c * 8;
        CP16(sdst + soff,             (const char*)(Ah + ga));
        CP16(sdst + TILEB + soff,     (const char*)(Al + ga));
        CP16(sdst + 2 * TILEB + soff, (const char*)(Bh + gb));
        CP16(sdst + 3 * TILEB + soff, (const char*)(Bl + gb));
    }
}

__global__ __launch_bounds__(256)
void mma_gemm_kernel(const __nv_bfloat16* __restrict__ Ah,
                     const __nv_bfloat16* __restrict__ Al,
                     const __nv_bfloat16* __restrict__ Bh,
                     const __nv_bfloat16* __restrict__ Bl,
                     const float* __restrict__ bias,
                     float* __restrict__ C, int N) {
    extern __shared__ char smem[];
    const uint32_t sb = smem_u32(smem);

    const int t    = threadIdx.x;
    const int lane = t & 31;
    const int w    = t >> 5;
    const int wm   = w & 1;
    const int wn   = w >> 1;
    const int m0   = blockIdx.y * 128;
    const int n0   = blockIdx.x * 128;

    float acc[4][4][4];
#pragma unroll
    for (int mi = 0; mi < 4; mi++)
#pragma unroll
        for (int ni = 0; ni < 4; ni++)
#pragma unroll
            for (int r = 0; r < 4; r++) acc[mi][ni][r] = 0.f;

    g2s_stage(sb,          Ah, Al, Bh, Bl, m0, n0, 0,  t); CP_COMMIT();
    g2s_stage(sb + STAGEB, Ah, Al, Bh, Bl, m0, n0, 32, t); CP_COMMIT();

    for (int kt = 0; kt < NKT; kt++) {
        if (kt < NKT - 1) { CP_WAIT(1); } else { CP_WAIT(0); }
        __syncthreads();

        const uint32_t st = sb + (uint32_t)(kt & 1) * STAGEB;
#pragma unroll
        for (int ks = 0; ks < 2; ks++) {
            uint32_t ah[4][4], al[4][4];
#pragma unroll
            for (int mi = 0; mi < 4; mi++) {
                uint32_t ra = st + (uint32_t)((wm * 64 + mi * 16 + (lane & 15)) * ROWB
                                              + ks * 32 + (lane >> 4) * 16);
                ldsm_x4(ah[mi], ra);
                ldsm_x4(al[mi], ra + TILEB);
            }
            uint32_t bh[4][2], bl[4][2];
#pragma unroll
            for (int nb = 0; nb < 2; nb++) {
                int g = lane >> 3;
                uint32_t rb = st + 2 * TILEB
                            + (uint32_t)((wn * 32 + nb * 16 + (g >> 1) * 8 + (lane & 7)) * ROWB
                                         + ks * 32 + (g & 1) * 16);
                ldsm_x4(&bh[2 * nb][0], rb);
                ldsm_x4(&bl[2 * nb][0], rb + TILEB);
            }
#pragma unroll
            for (int mi = 0; mi < 4; mi++)
#pragma unroll
                for (int ni = 0; ni < 4; ni++) {
                    mma16816(acc[mi][ni], ah[mi], bh[ni]);
                    mma16816(acc[mi][ni], ah[mi], bl[ni]);
                    mma16816(acc[mi][ni], al[mi], bh[ni]);
                }
        }
        __syncthreads();
        if (kt + 2 < NKT) {
            g2s_stage(sb + (uint32_t)(kt & 1) * STAGEB, Ah, Al, Bh, Bl,
                      m0, n0, (kt + 2) * 32, t);
            CP_COMMIT();
        }
    }

#pragma unroll
    for (int mi = 0; mi < 4; mi++) {
        int row = m0 + wm * 64 + mi * 16 + (lane >> 2);
#pragma unroll
        for (int ni = 0; ni < 4; ni++) {
            int col = n0 + wn * 32 + ni * 8 + (lane & 3) * 2;
            float b0 = bias[col], b1 = bias[col + 1];
            float2 v0 = {acc[mi][ni][0] + b0, acc[mi][ni][1] + b1};
            float2 v1 = {acc[mi][ni][2] + b0, acc[mi][ni][3] + b1};
            *(float2*)&C[(size_t)row * N + col]       = v0;
            *(float2*)&C[(size_t)(row + 8) * N + col] = v1;
        }
    }
}

// ---------------------------------------------------------------------------
// Attention pre-pass: g_qkv fp32 -> per-head bf16 hi/lo [bh][t][64] + sq-norms
// one warp per (token, head)
// ---------------------------------------------------------------------------
__device__ __forceinline__ float split_row2(const float* src, uint32_t* hi, uint32_t* lo,
                                            size_t u32idx, int lane) {
    float2 v = *(const float2*)(src + lane * 2);
    __nv_bfloat16 h0 = __float2bfloat16(v.x);
    __nv_bfloat16 h1 = __float2bfloat16(v.y);
    float r0 = v.x - __bfloat162float(h0);
    float r1 = v.y - __bfloat162float(h1);
    __nv_bfloat16 l0 = __float2bfloat16(r0);
    __nv_bfloat16 l1 = __float2bfloat16(r1);
    hi[u32idx + lane] = ((uint32_t)*(uint16_t*)&h1 << 16) | *(uint16_t*)&h0;
    lo[u32idx + lane] = ((uint32_t)*(uint16_t*)&l1 << 16) | *(uint16_t*)&l0;
    return fmaf(v.x, v.x, v.y * v.y);
}

__global__ __launch_bounds__(256)
void attn_prep(const float* __restrict__ qkv) {
    int gw   = (blockIdx.x * blockDim.x + threadIdx.x) >> 5;
    int lane = threadIdx.x & 31;
    if (gw >= MTOT * NHEAD) return;
    int h = gw & (NHEAD - 1);
    int n = gw >> 4;                       // token index 0..4095
    int b = n >> 11, tt = n & (TSEQ - 1);
    size_t src = (size_t)n * N1 + h * HDIM;
    size_t orow = ((size_t)(b * NHEAD + h) * TSEQ + tt) * HDIM;
    size_t u32 = orow >> 1;

    float qs = split_row2(g_qkv + src,            (uint32_t*)g_qhi, (uint32_t*)g_qlo, u32, lane);
    float ks = split_row2(g_qkv + src + CDIM,     (uint32_t*)g_khi, (uint32_t*)g_klo, u32, lane);
    (void)    split_row2(g_qkv + src + 2 * CDIM,  (uint32_t*)g_vhi, (uint32_t*)g_vlo, u32, lane);
#pragma unroll
    for (int o = 16; o; o >>= 1) {
        qs += __shfl_xor_sync(0xffffffffu, qs, o);
        ks += __shfl_xor_sync(0xffffffffu, ks, o);
    }
    if (lane == 0) {
        size_t ri = (size_t)(b * NHEAD + h) * TSEQ + tt;
        g_qsq[ri] = qs;
        g_ksq[ri] = ks;
    }
}

// ---------------------------------------------------------------------------
// FlashAttention-style Yat attention with HMMA (bf16 hi/lo splits everywhere)
// CTA: (qt, h, b); 8 warps x 16 q-rows = 128 q-rows; K-tiles of 64, 2 stages.
// ---------------------------------------------------------------------------
#define AROWB 144                       // 64 bf16 = 128B + 16B pad
#define QLOFF  18432                    // 128 * 144
#define SBASE  36864                    // after Q hi+lo
#define KLOFF  9216                     // 64 * 144
#define VHOFF  18432
#define VLOFF  27648
#define KSQOFF 36864
#define ASTG   37120                    // stage stride (incl. ksq 256B)
#define ATT_SMEM (SBASE + 2 * ASTG)     // 111104

__device__ __forceinline__ void load_kv(uint32_t dst,
                                        const char* kh, const char* kl,
                                        const char* vh, const char* vl,
                                        const char* ksq, int kt, int t) {
#pragma unroll
    for (int i = 0; i < 2; i++) {
        int idx = t + i * 256;
        int rr = idx >> 3, cc = idx & 7;
        uint32_t off = (uint32_t)(rr * AROWB + cc * 16);
        size_t gbyte = ((size_t)(kt * 64 + rr) * HDIM + cc * 8) * 2;
        CP16(dst + off,         kh + gbyte);
        CP16(dst + KLOFF + off, kl + gbyte);
        CP16(dst + VHOFF + off, vh + gbyte);
        CP16(dst + VLOFF + off, vl + gbyte);
    }
    if (t < 16) CP16(dst + KSQOFF + t * 16, ksq + (size_t)kt * 64 * 4 + t * 16);
}

__global__ __launch_bounds__(256, 2)
void yat_attn_mma(float* __restrict__ att) {
    extern __shared__ char smem[];
    const uint32_t sb = smem_u32(smem);

    const int t = threadIdx.x, lane = t & 31, w = t >> 5;
    const int h = blockIdx.y, b = blockIdx.z;
    const int qt = gridDim.x - 1 - blockIdx.x;     // heavy tiles first
    const int q0 = qt * 128;
    const int bh = b * NHEAD + h;
    const size_t hb = (size_t)bh * TSEQ * HDIM;

    const char* pQh = (const char*)(g_qhi + hb);
    const char* pQl = (const char*)(g_qlo + hb);
    const char* pKh = (const char*)(g_khi + hb);
    const char* pKl = (const char*)(g_klo + hb);
    const char* pVh = (const char*)(g_vhi + hb);
    const char* pVl = (const char*)(g_vlo + hb);
    const char* pKs = (const char*)(g_ksq + (size_t)bh * TSEQ);

    const int nkt = 2 * qt + 2;

    // group 0: Q tile (hi+lo)
#pragma unroll
    for (int i = 0; i < 4; i++) {
        int idx = t + i * 256;
        int r = idx >> 3, c = idx & 7;
        uint32_t d = sb + (uint32_t)(r * AROWB + c * 16);
        size_t gbyte = ((size_t)(q0 + r) * HDIM + c * 8) * 2;
        CP16(d,          pQh + gbyte);
        CP16(d + QLOFF,  pQl + gbyte);
    }
    CP_COMMIT();
    // groups 1,2: kv0, kv1
    load_kv(sb + SBASE,        pKh, pKl, pVh, pVl, pKs, 0, t); CP_COMMIT();
    load_kv(sb + SBASE + ASTG, pKh, pKl, pVh, pVl, pKs, 1, t); CP_COMMIT();

    const int rl  = lane >> 2;
    const int rg0 = q0 + w * 16 + rl;
    const int rg1 = rg0 + 8;
    const float qa0 = g_qsq[(size_t)bh * TSEQ + rg0] + EPS;
    const float qa1 = g_qsq[(size_t)bh * TSEQ + rg1] + EPS;

    float O[8][4];
#pragma unroll
    for (int dt = 0; dt < 8; dt++)
#pragma unroll
        for (int r = 0; r < 4; r++) O[dt][r] = 0.f;
    float m0 = -1e30f, m1 = -1e30f, l0 = 0.f, l1 = 0.f;

    for (int i = 0; i < nkt; i++) {
        if (i == nkt - 1) { CP_WAIT(0); } else { CP_WAIT(1); }
        __syncthreads();

        const uint32_t kb = sb + SBASE + (uint32_t)(i & 1) * ASTG;
        const char* kbp = smem + SBASE + (size_t)(i & 1) * ASTG;
        const float* ksqp = (const float*)(kbp + KSQOFF);
        const int k0 = i * 64;

        // ---- S = Q K^T (3-way split) ----
        float S[8][4];
#pragma unroll
        for (int nt = 0; nt < 8; nt++)
#pragma unroll
            for (int r = 0; r < 4; r++) S[nt][r] = 0.f;

        const int g = lane >> 3;
#pragma unroll
        for (int ks = 0; ks < 4; ks++) {
            uint32_t ah[4], al[4];
            uint32_t qaddr = sb + (uint32_t)((w * 16 + (lane & 15)) * AROWB
                                             + ks * 32 + (lane >> 4) * 16);
            ldsm_x4(ah, qaddr);
            ldsm_x4(al, qaddr + QLOFF);
#pragma unroll
            for (int nb = 0; nb < 4; nb++) {
                uint32_t bh4[4], bl4[4];
                uint32_t kaddr = kb + (uint32_t)((nb * 16 + (g >> 1) * 8 + (lane & 7)) * AROWB
                                                 + ks * 32 + (g & 1) * 16);
                ldsm_x4(bh4, kaddr);
                ldsm_x4(bl4, kaddr + KLOFF);
                mma16816(S[2 * nb],     ah, bh4);
                mma16816(S[2 * nb],     al, bh4);
                mma16816(S[2 * nb],     ah, bl4);
                mma16816(S[2 * nb + 1], ah, bh4 + 2);
                mma16816(S[2 * nb + 1], al, bh4 + 2);
                mma16816(S[2 * nb + 1], ah, bl4 + 2);
            }
        }

        // ---- scores + mask + online softmax (all on FMA pipe) ----
        float mx0 = -1e30f, mx1 = -1e30f;
#pragma unroll
        for (int nt = 0; nt < 8; nt++) {
            int cb = nt * 8 + 2 * (lane & 3);
            float ks0 = ksqp[cb], ks1 = ksqp[cb + 1];
            int cg = k0 + cb;
            float s00 = qa0 + ks0, s01 = qa0 + ks1;
            float s10 = qa1 + ks0, s11 = qa1 + ks1;
            float d, den, sl;
            d = S[nt][0]; den = fmaf(-2.f, d, s00);
            sl = d * d * rcp_fast(den) * LOG2E;
            if (cg > rg0)     sl = -1e30f;
            S[nt][0] = sl; mx0 = fmaxf(mx0, sl);
            d = S[nt][1]; den = fmaf(-2.f, d, s01);
            sl = d * d * rcp_fast(den) * LOG2E;
            if (cg + 1 > rg0) sl = -1e30f;
            S[nt][1] = sl; mx0 = fmaxf(mx0, sl);
            d = S[nt][2]; den = fmaf(-2.f, d, s10);
            sl = d * d * rcp_fast(den) * LOG2E;
            if (cg > rg1)     sl = -1e30f;
            S[nt][2] = sl; mx1 = fmaxf(mx1, sl);
            d = S[nt][3]; den = fmaf(-2.f, d, s11);
            sl = d * d * rcp_fast(den) * LOG2E;
            if (cg + 1 > rg1) sl = -1e30f;
            S[nt][3] = sl; mx1 = fmaxf(mx1, sl);
        }
        mx0 = fmaxf(mx0, __shfl_xor_sync(0xffffffffu, mx0, 1));
        mx0 = fmaxf(mx0, __shfl_xor_sync(0xffffffffu, mx0, 2));
        mx1 = fmaxf(mx1, __shfl_xor_sync(0xffffffffu, mx1, 1));
        mx1 = fmaxf(mx1, __shfl_xor_sync(0xffffffffu, mx1, 2));
        float mn0 = fmaxf(m0, mx0), mn1 = fmaxf(m1, mx1);
        float sc0 = exp2_fast(m0 - mn0), sc1 = exp2_fast(m1 - mn1);
        m0 = mn0; m1 = mn1;
        l0 *= sc0; l1 *= sc1;
#pragma unroll
        for (int dt = 0; dt < 8; dt++) {
            O[dt][0] *= sc0; O[dt][1] *= sc0;
            O[dt][2] *= sc1; O[dt][3] *= sc1;
        }

        // ---- p = exp2(sl - m), split to bf16 hi/lo, pack to A-fragments ----
        uint32_t pH[8][2], pL[8][2];
#pragma unroll
        for (int nt = 0; nt < 8; nt++) {
            float p0 = exp2_fast(S[nt][0] - mn0);
            float p1 = exp2_fast(S[nt][1] - mn0);
            float p2 = exp2_fast(S[nt][2] - mn1);
            float p3 = exp2_fast(S[nt][3] - mn1);
            l0 += p0 + p1;
            l1 += p2 + p3;
            uint32_t h0 = pack_bf16x2(p1, p0);
            uint32_t h1 = pack_bf16x2(p3, p2);
            pH[nt][0] = h0; pH[nt][1] = h1;
            float r0 = p0 - __int_as_float(h0 << 16);
            float r1 = p1 - __int_as_float(h0 & 0xFFFF0000u);
            float r2 = p2 - __int_as_float(h1 << 16);
            float r3 = p3 - __int_as_float(h1 & 0xFFFF0000u);
            pL[nt][0] = pack_bf16x2(r1, r0);
            pL[nt][1] = pack_bf16x2(r3, r2);
        }

        // ---- O += P V (3-way split), V via ldmatrix.trans ----
        const int vrow = (lane & 7) + ((lane >> 3) & 1) * 8;
        const int vcol = ((lane >> 4) & 1) * 16;
#pragma unroll
        for (int kc = 0; kc < 4; kc++) {
            uint32_t aH[4] = {pH[2 * kc][0], pH[2 * kc][1], pH[2 * kc + 1][0], pH[2 * kc + 1][1]};
            uint32_t aL[4] = {pL[2 * kc][0], pL[2 * kc][1], pL[2 * kc + 1][0], pL[2 * kc + 1][1]};
#pragma unroll
            for (int dp = 0; dp < 4; dp++) {
                uint32_t vaddr = kb + VHOFF
                               + (uint32_t)((kc * 16 + vrow) * AROWB + dp * 32 + vcol);
                uint32_t vh4[4], vl4[4];
                ldsm_x4t(vh4, vaddr);
                ldsm_x4t(vl4, vaddr + KLOFF);   // VLOFF - VHOFF == KLOFF
                mma16816(O[2 * dp],     aH, vh4);
                mma16816(O[2 * dp],     aL, vh4);
                mma16816(O[2 * dp],     aH, vl4);
                mma16816(O[2 * dp + 1], aH, vh4 + 2);
                mma16816(O[2 * dp + 1], aL, vh4 + 2);
                mma16816(O[2 * dp + 1], aH, vl4 + 2);
            }
        }

        __syncthreads();
        if (i + 2 < nkt) {
            load_kv(kb, pKh, pKl, pVh, pVl, pKs, i + 2, t);
            CP_COMMIT();
        }
    }

    // ---- finalize: normalize and store fp32 ----
    l0 += __shfl_xor_sync(0xffffffffu, l0, 1);
    l0 += __shfl_xor_sync(0xffffffffu, l0, 2);
    l1 += __shfl_xor_sync(0xffffffffu, l1, 1);
    l1 += __shfl_xor_sync(0xffffffffu, l1, 2);
    float i0 = __fdividef(1.f, l0);
    float i1 = __fdividef(1.f, l1);

    float* o0 = att + ((size_t)(b * TSEQ + rg0)) * CDIM + h * HDIM + 2 * (lane & 3);
    float* o1 = att + ((size_t)(b * TSEQ + rg1)) * CDIM + h * HDIM + 2 * (lane & 3);
#pragma unroll
    for (int dt = 0; dt < 8; dt++) {
        float2 v0 = {O[dt][0] * i0, O[dt][1] * i0};
        float2 v1 = {O[dt][2] * i1, O[dt][3] * i1};
        *(float2*)(o0 + dt * 8) = v0;
        *(float2*)(o1 + dt * 8) = v1;
    }
}

// ---------------------------------------------------------------------------
// Launch
// ---------------------------------------------------------------------------
extern "C" void kernel_launch(void* const* d_in, const int* in_sizes, int n_in,
                              void* d_out, int out_size) {
    const float* x     = (const float*)d_in[0];
    const float* w_qkv = (const float*)d_in[1];
    const float* b_qkv = (const float*)d_in[2];
    const float* w_out = (const float*)d_in[3];
    const float* b_out = (const float*)d_in[4];
    float* out = (float*)d_out;

    void *p_qkv, *p_att, *p_xhi, *p_xlo, *p_wqh, *p_wql, *p_woh, *p_wol, *p_ahi, *p_alo;
    cudaGetSymbolAddress(&p_qkv, g_qkv);
    cudaGetSymbolAddress(&p_att, g_att);
    cudaGetSymbolAddress(&p_xhi, g_xhi);
    cudaGetSymbolAddress(&p_xlo, g_xlo);
    cudaGetSymbolAddress(&p_wqh, g_wqkvT_hi);
    cudaGetSymbolAddress(&p_wql, g_wqkvT_lo);
    cudaGetSymbolAddress(&p_woh, g_woT_hi);
    cudaGetSymbolAddress(&p_wol, g_woT_lo);
    cudaGetSymbolAddress(&p_ahi, g_atthi);
    cudaGetSymbolAddress(&p_alo, g_attlo);

    static bool attr_done = false;
    if (!attr_done) {
        cudaFuncSetAttribute(mma_gemm_kernel,
                             cudaFuncAttributeMaxDynamicSharedMemorySize, GEMM_SMEM);
        cudaFuncSetAttribute(yat_attn_mma,
                             cudaFuncAttributeMaxDynamicSharedMemorySize, ATT_SMEM);
        attr_done = true;
    }

    // 0) split x, transpose+split weights
    {
        int n4 = MTOT * KD / 4;
        split_kernel<<<(n4 + 255) / 256, 256>>>(x, (__nv_bfloat16*)p_xhi,
                                                (__nv_bfloat16*)p_xlo, n4);
        dim3 g1(N1 / 32, KD / 32);
        transpose_split_kernel<<<g1, 256>>>(w_qkv, (__nv_bfloat16*)p_wqh,
                                            (__nv_bfloat16*)p_wql, KD, N1);
        dim3 g2(CDIM / 32, KD / 32);
        transpose_split_kernel<<<g2, 256>>>(w_out, (__nv_bfloat16*)p_woh,
                                            (__nv_bfloat16*)p_wol, KD, CDIM);
    }

    // 1) QKV projection
    {
        dim3 grid(N1 / 128, MTOT / 128);
        mma_gemm_kernel<<<grid, 256, GEMM_SMEM>>>(
            (const __nv_bfloat16*)p_xhi, (const __nv_bfloat16*)p_xlo,
            (const __nv_bfloat16*)p_wqh, (const __nv_bfloat16*)p_wql,
            b_qkv, (float*)p_qkv, N1);
    }

    // 2) attention pre-pass + HMMA flash attention
    {
        attn_prep<<<(MTOT * NHEAD) / 8, 256>>>((const float*)p_qkv);
        dim3 grid(TSEQ / 128, NHEAD, BSZ);
        yat_attn_mma<<<grid, 256, ATT_SMEM>>>((float*)p_att);
    }

    // 3) split attention output, output projection
    {
        int n4 = MTOT * CDIM / 4;
        split_kernel<<<(n4 + 255) / 256, 256>>>((const float*)p_att,
                                                (__nv_bfloat16*)p_ahi,
                                                (__nv_bfloat16*)p_alo, n4);
        dim3 grid(CDIM / 128, MTOT / 128);
        mma_gemm_kernel<<<grid, 256, GEMM_SMEM>>>(
            (const __nv_bfloat16*)p_ahi, (const __nv_bfloat16*)p_alo,
            (const __nv_bfloat16*)p_woh, (const __nv_bfloat16*)p_wol,
            b_out, out, CDIM);
    }
}

// round 8
// speedup vs baseline: 3.3068x; 1.0136x over previous
#include <cuda_runtime.h>
#include <cuda_bf16.h>
#include <math.h>
#include <stdint.h>

#define BSZ 2
#define TSEQ 2048
#define CDIM 1024
#define NHEAD 16
#define HDIM 64
#define EPS 1e-6f
#define LOG2E 1.4426950408889634f

#define MTOT (BSZ * TSEQ)          // 4096
#define N1 (3 * CDIM)              // 3072
#define KD CDIM                    // 1024

// ---------------------------------------------------------------------------
// Scratch (__device__ globals; no allocation allowed)
// ---------------------------------------------------------------------------
__device__ __nv_bfloat16 g_xhi[(size_t)MTOT * KD];
__device__ __nv_bfloat16 g_xlo[(size_t)MTOT * KD];
__device__ __nv_bfloat16 g_wqkvT_hi[(size_t)N1 * KD];
__device__ __nv_bfloat16 g_wqkvT_lo[(size_t)N1 * KD];
__device__ __nv_bfloat16 g_woT_hi[(size_t)CDIM * KD];
__device__ __nv_bfloat16 g_woT_lo[(size_t)CDIM * KD];
__device__ __nv_bfloat16 g_atthi[(size_t)MTOT * KD];
__device__ __nv_bfloat16 g_attlo[(size_t)MTOT * KD];

// attention operands: [b*H+h][t][64] bf16 hi/lo + row sq-norms
#define BHT ((size_t)BSZ * NHEAD * TSEQ)
__device__ __nv_bfloat16 g_qhi[BHT * HDIM];
__device__ __nv_bfloat16 g_qlo[BHT * HDIM];
__device__ __nv_bfloat16 g_khi[BHT * HDIM];
__device__ __nv_bfloat16 g_klo[BHT * HDIM];
__device__ __nv_bfloat16 g_vhi[BHT * HDIM];
__device__ __nv_bfloat16 g_vlo[BHT * HDIM];
__device__ float g_qsq[BHT];
__device__ float g_ksq[BHT];

// ---------------------------------------------------------------------------
// PTX helpers (baseline sm_80+ instructions only — compute_103-safe)
// ---------------------------------------------------------------------------
__device__ __forceinline__ uint32_t smem_u32(const void* p) {
    uint32_t a;
    asm("{ .reg .u64 t; cvta.to.shared.u64 t, %1; cvt.u32.u64 %0, t; }"
        : "=r"(a) : "l"(p));
    return a;
}

#define CP16(dst, src) \
    asm volatile("cp.async.cg.shared.global [%0], [%1], 16;" \
                 :: "r"(dst), "l"(src))
#define CP_COMMIT() asm volatile("cp.async.commit_group;" ::: "memory")
#define CP_WAIT(n)  asm volatile("cp.async.wait_group %0;" :: "n"(n) : "memory")

__device__ __forceinline__ void ldsm_x4(uint32_t* r, uint32_t addr) {
    asm volatile("ldmatrix.sync.aligned.m8n8.x4.shared.b16 {%0,%1,%2,%3}, [%4];"
                 : "=r"(r[0]), "=r"(r[1]), "=r"(r[2]), "=r"(r[3]) : "r"(addr));
}
__device__ __forceinline__ void ldsm_x4t(uint32_t* r, uint32_t addr) {
    asm volatile("ldmatrix.sync.aligned.m8n8.x4.trans.shared.b16 {%0,%1,%2,%3}, [%4];"
                 : "=r"(r[0]), "=r"(r[1]), "=r"(r[2]), "=r"(r[3]) : "r"(addr));
}

__device__ __forceinline__ void mma16816(float* c, const uint32_t* a, const uint32_t* b) {
    asm volatile(
        "mma.sync.aligned.m16n8k16.row.col.f32.bf16.bf16.f32 "
        "{%0,%1,%2,%3}, {%4,%5,%6,%7}, {%8,%9}, {%0,%1,%2,%3};"
        : "+f"(c[0]), "+f"(c[1]), "+f"(c[2]), "+f"(c[3])
        : "r"(a[0]), "r"(a[1]), "r"(a[2]), "r"(a[3]), "r"(b[0]), "r"(b[1]));
}

__device__ __forceinline__ uint32_t pack_bf16x2(float hi, float lo) {
    uint32_t r;
    asm("cvt.rn.bf16x2.f32 %0, %1, %2;" : "=r"(r) : "f"(hi), "f"(lo));
    return r;
}

// exp2 on FMA pipe: magic-constant round + deg-5 poly on [-0.5, 0.5]
__device__ __forceinline__ float exp2_fast(float x) {
    x = fmaxf(x, -126.f);
    float t = x + 12582912.f;
    int   i = __float_as_int(t) - 0x4B400000;
    float f = x - (t - 12582912.f);
    float p =            1.33336498e-3f;
    p = fmaf(p, f, 9.61793571e-3f);
    p = fmaf(p, f, 5.55041087e-2f);
    p = fmaf(p, f, 2.40226507e-1f);
    p = fmaf(p, f, 6.93147182e-1f);
    p = fmaf(p, f, 1.0f);
    return __int_as_float(__float_as_int(p) + (i << 23));
}

// rcp on FMA pipe: bit trick + 3 Newton iterations (d > 0)
__device__ __forceinline__ float rcp_fast(float d) {
    float y = __int_as_float(0x7EF311C3 - __float_as_int(d));
    y = y * fmaf(-d, y, 2.0f);
    y = y * fmaf(-d, y, 2.0f);
    y = y * fmaf(-d, y, 2.0f);
    return y;
}

// ---------------------------------------------------------------------------
// Pre-pass: split fp32 -> bf16 hi/lo (elementwise)
// ---------------------------------------------------------------------------
__global__ void split_kernel(const float* __restrict__ src,
                             __nv_bfloat16* __restrict__ hi,
                             __nv_bfloat16* __restrict__ lo, int n4) {
    int i = blockIdx.x * blockDim.x + threadIdx.x;
    if (i >= n4) return;
    float4 v = ((const float4*)src)[i];
    float a[4] = {v.x, v.y, v.z, v.w};
    ushort4 hv, lv;
    unsigned short* hp = &hv.x;
    unsigned short* lp = &lv.x;
#pragma unroll
    for (int j = 0; j < 4; j++) {
        __nv_bfloat16 h = __float2bfloat16(a[j]);
        float r = a[j] - __bfloat162float(h);
        __nv_bfloat16 l = __float2bfloat16(r);
        hp[j] = *(unsigned short*)&h;
        lp[j] = *(unsigned short*)&l;
    }
    ((ushort4*)hi)[i] = hv;
    ((ushort4*)lo)[i] = lv;
}

// ---------------------------------------------------------------------------
// Pre-pass: transpose + split  W[K,N] fp32 -> Wt_hi/lo[N,K] bf16
// ---------------------------------------------------------------------------
__global__ __launch_bounds__(256)
void transpose_split_kernel(const float* __restrict__ W,
                            __nv_bfloat16* __restrict__ hi,
                            __nv_bfloat16* __restrict__ lo, int K, int N) {
    __shared__ float tile[32][33];
    int n0 = blockIdx.x * 32, k0 = blockIdx.y * 32;
    int tx = threadIdx.x & 31, ty = threadIdx.x >> 5;
#pragma unroll
    for (int j = 0; j < 32; j += 8)
        tile[ty + j][tx] = W[(size_t)(k0 + ty + j) * N + n0 + tx];
    __syncthreads();
#pragma unroll
    for (int j = 0; j < 32; j += 8) {
        float v = tile[tx][ty + j];
        __nv_bfloat16 h = __float2bfloat16(v);
        float r = v - __bfloat162float(h);
        hi[(size_t)(n0 + ty + j) * K + k0 + tx] = h;
        lo[(size_t)(n0 + ty + j) * K + k0 + tx] = __float2bfloat16(r);
    }
}

// ---------------------------------------------------------------------------
// sq-norm kernel: reconstruct hi+lo bf16 rows, write |row|^2 (q and k)
// one warp per row of 64
// ---------------------------------------------------------------------------
__global__ __launch_bounds__(256)
void sqnorm_kernel() {
    const uint32_t* hi = blockIdx.y ? (const uint32_t*)g_khi : (const uint32_t*)g_qhi;
    const uint32_t* lo = blockIdx.y ? (const uint32_t*)g_klo : (const uint32_t*)g_qlo;
    float* out = blockIdx.y ? g_ksq : g_qsq;
    size_t gw = (size_t)blockIdx.x * 8 + (threadIdx.x >> 5);
    int lane = threadIdx.x & 31;
    uint32_t h = hi[gw * 32 + lane], l = lo[gw * 32 + lane];
    float f0 = __int_as_float(h << 16) + __int_as_float(l << 16);
    float f1 = __int_as_float(h & 0xFFFF0000u) + __int_as_float(l & 0xFFFF0000u);
    float s = fmaf(f0, f0, f1 * f1);
#pragma unroll
    for (int o = 16; o; o >>= 1) s += __shfl_xor_sync(0xffffffffu, s, o);
    if (lane == 0) out[gw] = s;
}

// ---------------------------------------------------------------------------
// HMMA GEMM mainloop: acc = (Ah+Al)[M,K] @ (Bh+Bl)[N,K]^T, K=1024
// CTA 128x128, BK=32, 2-stage cp.async. Pass-major MMA order (RAW-chain free).
// ---------------------------------------------------------------------------
#define ROWB 80
#define TILEB (128 * ROWB)
#define STAGEB (4 * TILEB)
#define GEMM_SMEM (2 * STAGEB)
#define NKT (KD / 32)

__device__ __forceinline__ void g2s_stage(uint32_t sdst,
                                          const __nv_bfloat16* Ah, const __nv_bfloat16* Al,
                                          const __nv_bfloat16* Bh, const __nv_bfloat16* Bl,
                                          int m0, int n0, int k0, int t) {
#pragma unroll
    for (int i = 0; i < 2; i++) {
        int idx = t + i * 256;
        int r = idx >> 2;
        int c = idx & 3;
        uint32_t soff = (uint32_t)(r * ROWB + c * 16);
        size_t ga = (size_t)(m0 + r) * KD + k0 + c * 8;
        size_t gb = (size_t)(n0 + r) * KD + k0 + c * 8;
        CP16(sdst + soff,             (const char*)(Ah + ga));
        CP16(sdst + TILEB + soff,     (const char*)(Al + ga));
        CP16(sdst + 2 * TILEB + soff, (const char*)(Bh + gb));
        CP16(sdst + 3 * TILEB + soff, (const char*)(Bl + gb));
    }
}

__device__ __forceinline__ void gemm_mainloop(
        uint32_t sb, const __nv_bfloat16* Ah, const __nv_bfloat16* Al,
        const __nv_bfloat16* Bh, const __nv_bfloat16* Bl,
        int m0, int n0, int t, float acc[4][4][4]) {
    const int lane = t & 31;
    const int w    = t >> 5;
    const int wm   = w & 1;
    const int wn   = w >> 1;

    g2s_stage(sb,          Ah, Al, Bh, Bl, m0, n0, 0,  t); CP_COMMIT();
    g2s_stage(sb + STAGEB, Ah, Al, Bh, Bl, m0, n0, 32, t); CP_COMMIT();

    for (int kt = 0; kt < NKT; kt++) {
        if (kt < NKT - 1) { CP_WAIT(1); } else { CP_WAIT(0); }
        __syncthreads();

        const uint32_t st = sb + (uint32_t)(kt & 1) * STAGEB;
#pragma unroll
        for (int ks = 0; ks < 2; ks++) {
            uint32_t ah[4][4], al[4][4];
#pragma unroll
            for (int mi = 0; mi < 4; mi++) {
                uint32_t ra = st + (uint32_t)((wm * 64 + mi * 16 + (lane & 15)) * ROWB
                                              + ks * 32 + (lane >> 4) * 16);
                ldsm_x4(ah[mi], ra);
                ldsm_x4(al[mi], ra + TILEB);
            }
            uint32_t bh[4][2], bl[4][2];
#pragma unroll
            for (int nb = 0; nb < 2; nb++) {
                int g = lane >> 3;
                uint32_t rb = st + 2 * TILEB
                            + (uint32_t)((wn * 32 + nb * 16 + (g >> 1) * 8 + (lane & 7)) * ROWB
                                         + ks * 32 + (g & 1) * 16);
                ldsm_x4(&bh[2 * nb][0], rb);
                ldsm_x4(&bl[2 * nb][0], rb + TILEB);
            }
            // pass-major: 16 independent accumulators between reuses
#pragma unroll
            for (int mi = 0; mi < 4; mi++)
#pragma unroll
                for (int ni = 0; ni < 4; ni++) mma16816(acc[mi][ni], ah[mi], bh[ni]);
#pragma unroll
            for (int mi = 0; mi < 4; mi++)
#pragma unroll
                for (int ni = 0; ni < 4; ni++) mma16816(acc[mi][ni], ah[mi], bl[ni]);
#pragma unroll
            for (int mi = 0; mi < 4; mi++)
#pragma unroll
                for (int ni = 0; ni < 4; ni++) mma16816(acc[mi][ni], al[mi], bh[ni]);
        }
        __syncthreads();
        if (kt + 2 < NKT) {
            g2s_stage(sb + (uint32_t)(kt & 1) * STAGEB, Ah, Al, Bh, Bl,
                      m0, n0, (kt + 2) * 32, t);
            CP_COMMIT();
        }
    }
}

// GEMM2: plain fp32 + bias epilogue (writes final output)
__global__ __launch_bounds__(256)
void mma_gemm_kernel(const __nv_bfloat16* __restrict__ Ah,
                     const __nv_bfloat16* __restrict__ Al,
                     const __nv_bfloat16* __restrict__ Bh,
                     const __nv_bfloat16* __restrict__ Bl,
                     const float* __restrict__ bias,
                     float* __restrict__ C, int N) {
    extern __shared__ char smem[];
    const uint32_t sb = smem_u32(smem);
    const int t = threadIdx.x, lane = t & 31, w = t >> 5;
    const int wm = w & 1, wn = w >> 1;
    const int m0 = blockIdx.y * 128, n0 = blockIdx.x * 128;

    float acc[4][4][4];
#pragma unroll
    for (int mi = 0; mi < 4; mi++)
#pragma unroll
        for (int ni = 0; ni < 4; ni++)
#pragma unroll
            for (int r = 0; r < 4; r++) acc[mi][ni][r] = 0.f;

    gemm_mainloop(sb, Ah, Al, Bh, Bl, m0, n0, t, acc);

#pragma unroll
    for (int mi = 0; mi < 4; mi++) {
        int row = m0 + wm * 64 + mi * 16 + (lane >> 2);
#pragma unroll
        for (int ni = 0; ni < 4; ni++) {
            int col = n0 + wn * 32 + ni * 8 + (lane & 3) * 2;
            float b0 = bias[col], b1 = bias[col + 1];
            float2 v0 = {acc[mi][ni][0] + b0, acc[mi][ni][1] + b1};
            float2 v1 = {acc[mi][ni][2] + b0, acc[mi][ni][3] + b1};
            *(float2*)&C[(size_t)row * N + col]       = v0;
            *(float2*)&C[(size_t)(row + 8) * N + col] = v1;
        }
    }
}

// GEMM1: fused epilogue -> per-head bf16 hi/lo q/k/v (skips fp32 round-trip)
__global__ __launch_bounds__(256)
void mma_gemm_qkv_kernel(const __nv_bfloat16* __restrict__ Ah,
                         const __nv_bfloat16* __restrict__ Al,
                         const __nv_bfloat16* __restrict__ Bh,
                         const __nv_bfloat16* __restrict__ Bl,
                         const float* __restrict__ bias) {
    extern __shared__ char smem[];
    const uint32_t sb = smem_u32(smem);
    const int t = threadIdx.x, lane = t & 31, w = t >> 5;
    const int wm = w & 1, wn = w >> 1;
    const int m0 = blockIdx.y * 128, n0 = blockIdx.x * 128;

    float acc[4][4][4];
#pragma unroll
    for (int mi = 0; mi < 4; mi++)
#pragma unroll
        for (int ni = 0; ni < 4; ni++)
#pragma unroll
            for (int r = 0; r < 4; r++) acc[mi][ni][r] = 0.f;

    gemm_mainloop(sb, Ah, Al, Bh, Bl, m0, n0, t, acc);

    const int sec = n0 >> 10;     // 0=q, 1=k, 2=v (tile fully within one section)
    uint32_t* ph = sec == 0 ? (uint32_t*)g_qhi : sec == 1 ? (uint32_t*)g_khi : (uint32_t*)g_vhi;
    uint32_t* pl = sec == 0 ? (uint32_t*)g_qlo : sec == 1 ? (uint32_t*)g_klo : (uint32_t*)g_vlo;

#pragma unroll
    for (int mi = 0; mi < 4; mi++) {
        int row = m0 + wm * 64 + mi * 16 + (lane >> 2);
        int b   = row >> 11, tok = row & (TSEQ - 1);
#pragma unroll
        for (int ni = 0; ni < 4; ni++) {
            int col  = n0 + wn * 32 + ni * 8 + (lane & 3) * 2;
            int head = (col >> 6) & (NHEAD - 1);
            int d    = col & 63;
            size_t base = ((size_t)(b * NHEAD + head) * TSEQ) * 32 + (d >> 1);
            float b0 = bias[col], b1 = bias[col + 1];
#pragma unroll
            for (int r2 = 0; r2 < 2; r2++) {
                float v0 = acc[mi][ni][2 * r2]     + b0;
                float v1 = acc[mi][ni][2 * r2 + 1] + b1;
                uint32_t hv = pack_bf16x2(v1, v0);
                float r0 = v0 - __int_as_float(hv << 16);
                float r1 = v1 - __int_as_float(hv & 0xFFFF0000u);
                uint32_t lv = pack_bf16x2(r1, r0);
                size_t idx = base + (size_t)(tok + r2 * 8) * 32;
                ph[idx] = hv;
                pl[idx] = lv;
            }
        }
    }
}

// ---------------------------------------------------------------------------
// FlashAttention-style Yat attention with HMMA; fused bf16-split epilogue.
// CTA: (qt, h, b); 8 warps x 16 q-rows = 128 q-rows; K-tiles of 64, 2 stages.
// ---------------------------------------------------------------------------
#define AROWB 144
#define QLOFF  18432
#define SBASE  36864
#define KLOFF  9216
#define VHOFF  18432
#define VLOFF  27648
#define KSQOFF 36864
#define ASTG   37120
#define ATT_SMEM (SBASE + 2 * ASTG)

__device__ __forceinline__ void load_kv(uint32_t dst,
                                        const char* kh, const char* kl,
                                        const char* vh, const char* vl,
                                        const char* ksq, int kt, int t) {
#pragma unroll
    for (int i = 0; i < 2; i++) {
        int idx = t + i * 256;
        int rr = idx >> 3, cc = idx & 7;
        uint32_t off = (uint32_t)(rr * AROWB + cc * 16);
        size_t gbyte = ((size_t)(kt * 64 + rr) * HDIM + cc * 8) * 2;
        CP16(dst + off,         kh + gbyte);
        CP16(dst + KLOFF + off, kl + gbyte);
        CP16(dst + VHOFF + off, vh + gbyte);
        CP16(dst + VLOFF + off, vl + gbyte);
    }
    if (t < 16) CP16(dst + KSQOFF + t * 16, ksq + (size_t)kt * 64 * 4 + t * 16);
}

__global__ __launch_bounds__(256, 2)
void yat_attn_mma() {
    extern __shared__ char smem[];
    const uint32_t sb = smem_u32(smem);

    const int t = threadIdx.x, lane = t & 31, w = t >> 5;
    const int h = blockIdx.y, b = blockIdx.z;
    const int qt = gridDim.x - 1 - blockIdx.x;
    const int q0 = qt * 128;
    const int bh = b * NHEAD + h;
    const size_t hb = (size_t)bh * TSEQ * HDIM;

    const char* pQh = (const char*)(g_qhi + hb);
    const char* pQl = (const char*)(g_qlo + hb);
    const char* pKh = (const char*)(g_khi + hb);
    const char* pKl = (const char*)(g_klo + hb);
    const char* pVh = (const char*)(g_vhi + hb);
    const char* pVl = (const char*)(g_vlo + hb);
    const char* pKs = (const char*)(g_ksq + (size_t)bh * TSEQ);

    const int nkt = 2 * qt + 2;

#pragma unroll
    for (int i = 0; i < 4; i++) {
        int idx = t + i * 256;
        int r = idx >> 3, c = idx & 7;
        uint32_t d = sb + (uint32_t)(r * AROWB + c * 16);
        size_t gbyte = ((size_t)(q0 + r) * HDIM + c * 8) * 2;
        CP16(d,          pQh + gbyte);
        CP16(d + QLOFF,  pQl + gbyte);
    }
    CP_COMMIT();
    load_kv(sb + SBASE,        pKh, pKl, pVh, pVl, pKs, 0, t); CP_COMMIT();
    load_kv(sb + SBASE + ASTG, pKh, pKl, pVh, pVl, pKs, 1, t); CP_COMMIT();

    const int rl  = lane >> 2;
    const int rg0 = q0 + w * 16 + rl;
    const int rg1 = rg0 + 8;
    const float qa0 = g_qsq[(size_t)bh * TSEQ + rg0] + EPS;
    const float qa1 = g_qsq[(size_t)bh * TSEQ + rg1] + EPS;

    float O[8][4];
#pragma unroll
    for (int dt = 0; dt < 8; dt++)
#pragma unroll
        for (int r = 0; r < 4; r++) O[dt][r] = 0.f;
    float m0 = -1e30f, m1 = -1e30f, l0 = 0.f, l1 = 0.f;

    for (int i = 0; i < nkt; i++) {
        if (i == nkt - 1) { CP_WAIT(0); } else { CP_WAIT(1); }
        __syncthreads();

        const uint32_t kb = sb + SBASE + (uint32_t)(i & 1) * ASTG;
        const char* kbp = smem + SBASE + (size_t)(i & 1) * ASTG;
        const float* ksqp = (const float*)(kbp + KSQOFF);
        const int k0 = i * 64;

        // ---- S = Q K^T (3-way split), pairwise-interleaved accumulators ----
        float S[8][4];
#pragma unroll
        for (int nt = 0; nt < 8; nt++)
#pragma unroll
            for (int r = 0; r < 4; r++) S[nt][r] = 0.f;

        const int g = lane >> 3;
#pragma unroll
        for (int ks = 0; ks < 4; ks++) {
            uint32_t ah[4], al[4];
            uint32_t qaddr = sb + (uint32_t)((w * 16 + (lane & 15)) * AROWB
                                             + ks * 32 + (lane >> 4) * 16);
            ldsm_x4(ah, qaddr);
            ldsm_x4(al, qaddr + QLOFF);
#pragma unroll
            for (int nbp = 0; nbp < 4; nbp += 2) {
                uint32_t bhA[4], blA[4], bhB[4], blB[4];
                uint32_t kaddrA = kb + (uint32_t)((nbp * 16 + (g >> 1) * 8 + (lane & 7)) * AROWB
                                                  + ks * 32 + (g & 1) * 16);
                uint32_t kaddrB = kaddrA + 16 * AROWB;
                ldsm_x4(bhA, kaddrA);
                ldsm_x4(blA, kaddrA + KLOFF);
                ldsm_x4(bhB, kaddrB);
                ldsm_x4(blB, kaddrB + KLOFF);
                mma16816(S[2 * nbp],     ah, bhA);
                mma16816(S[2 * nbp + 1], ah, bhA + 2);
                mma16816(S[2 * nbp + 2], ah, bhB);
                mma16816(S[2 * nbp + 3], ah, bhB + 2);
                mma16816(S[2 * nbp],     al, bhA);
                mma16816(S[2 * nbp + 1], al, bhA + 2);
                mma16816(S[2 * nbp + 2], al, bhB);
                mma16816(S[2 * nbp + 3], al, bhB + 2);
                mma16816(S[2 * nbp],     ah, blA);
                mma16816(S[2 * nbp + 1], ah, blA + 2);
                mma16816(S[2 * nbp + 2], ah, blB);
                mma16816(S[2 * nbp + 3], ah, blB + 2);
            }
        }

        // ---- scores + mask + online softmax (FMA pipe only) ----
        float mx0 = -1e30f, mx1 = -1e30f;
#pragma unroll
        for (int nt = 0; nt < 8; nt++) {
            int cb = nt * 8 + 2 * (lane & 3);
            float ks0 = ksqp[cb], ks1 = ksqp[cb + 1];
            int cg = k0 + cb;
            float s00 = qa0 + ks0, s01 = qa0 + ks1;
            float s10 = qa1 + ks0, s11 = qa1 + ks1;
            float d, den, sl;
            d = S[nt][0]; den = fmaf(-2.f, d, s00);
            sl = d * d * rcp_fast(den) * LOG2E;
            if (cg > rg0)     sl = -1e30f;
            S[nt][0] = sl; mx0 = fmaxf(mx0, sl);
            d = S[nt][1]; den = fmaf(-2.f, d, s01);
            sl = d * d * rcp_fast(den) * LOG2E;
            if (cg + 1 > rg0) sl = -1e30f;
            S[nt][1] = sl; mx0 = fmaxf(mx0, sl);
            d = S[nt][2]; den = fmaf(-2.f, d, s10);
            sl = d * d * rcp_fast(den) * LOG2E;
            if (cg > rg1)     sl = -1e30f;
            S[nt][2] = sl; mx1 = fmaxf(mx1, sl);
            d = S[nt][3]; den = fmaf(-2.f, d, s11);
            sl = d * d * rcp_fast(den) * LOG2E;
            if (cg + 1 > rg1) sl = -1e30f;
            S[nt][3] = sl; mx1 = fmaxf(mx1, sl);
        }
        mx0 = fmaxf(mx0, __shfl_xor_sync(0xffffffffu, mx0, 1));
        mx0 = fmaxf(mx0, __shfl_xor_sync(0xffffffffu, mx0, 2));
        mx1 = fmaxf(mx1, __shfl_xor_sync(0xffffffffu, mx1, 1));
        mx1 = fmaxf(mx1, __shfl_xor_sync(0xffffffffu, mx1, 2));
        float mn0 = fmaxf(m0, mx0), mn1 = fmaxf(m1, mx1);
        float sc0 = exp2_fast(m0 - mn0), sc1 = exp2_fast(m1 - mn1);
        m0 = mn0; m1 = mn1;
        l0 *= sc0; l1 *= sc1;
#pragma unroll
        for (int dt = 0; dt < 8; dt++) {
            O[dt][0] *= sc0; O[dt][1] *= sc0;
            O[dt][2] *= sc1; O[dt][3] *= sc1;
        }

        // ---- p = exp2(sl - m), split to bf16 hi/lo A-fragments ----
        uint32_t pH[8][2], pL[8][2];
#pragma unroll
        for (int nt = 0; nt < 8; nt++) {
            float p0 = exp2_fast(S[nt][0] - mn0);
            float p1 = exp2_fast(S[nt][1] - mn0);
            float p2 = exp2_fast(S[nt][2] - mn1);
            float p3 = exp2_fast(S[nt][3] - mn1);
            l0 += p0 + p1;
            l1 += p2 + p3;
            uint32_t h0 = pack_bf16x2(p1, p0);
            uint32_t h1 = pack_bf16x2(p3, p2);
            pH[nt][0] = h0; pH[nt][1] = h1;
            float r0 = p0 - __int_as_float(h0 << 16);
            float r1 = p1 - __int_as_float(h0 & 0xFFFF0000u);
            float r2 = p2 - __int_as_float(h1 << 16);
            float r3 = p3 - __int_as_float(h1 & 0xFFFF0000u);
            pL[nt][0] = pack_bf16x2(r1, r0);
            pL[nt][1] = pack_bf16x2(r3, r2);
        }

        // ---- O += P V (3-way split), pairwise-interleaved dp accumulators ----
        const int vrow = (lane & 7) + ((lane >> 3) & 1) * 8;
        const int vcol = ((lane >> 4) & 1) * 16;
#pragma unroll
        for (int kc = 0; kc < 4; kc++) {
            uint32_t aH[4] = {pH[2 * kc][0], pH[2 * kc][1], pH[2 * kc + 1][0], pH[2 * kc + 1][1]};
            uint32_t aL[4] = {pL[2 * kc][0], pL[2 * kc][1], pL[2 * kc + 1][0], pL[2 * kc + 1][1]};
#pragma unroll
            for (int dpp = 0; dpp < 4; dpp += 2) {
                uint32_t vaddrA = kb + VHOFF
                                + (uint32_t)((kc * 16 + vrow) * AROWB + dpp * 32 + vcol);
                uint32_t vaddrB = vaddrA + 32;
                uint32_t vhA[4], vlA[4], vhB[4], vlB[4];
                ldsm_x4t(vhA, vaddrA);
                ldsm_x4t(vlA, vaddrA + KLOFF);
                ldsm_x4t(vhB, vaddrB);
                ldsm_x4t(vlB, vaddrB + KLOFF);
                mma16816(O[2 * dpp],     aH, vhA);
                mma16816(O[2 * dpp + 1], aH, vhA + 2);
                mma16816(O[2 * dpp + 2], aH, vhB);
                mma16816(O[2 * dpp + 3], aH, vhB + 2);
                mma16816(O[2 * dpp],     aL, vhA);
                mma16816(O[2 * dpp + 1], aL, vhA + 2);
                mma16816(O[2 * dpp + 2], aL, vhB);
                mma16816(O[2 * dpp + 3], aL, vhB + 2);
                mma16816(O[2 * dpp],     aH, vlA);
                mma16816(O[2 * dpp + 1], aH, vlA + 2);
                mma16816(O[2 * dpp + 2], aH, vlB);
                mma16816(O[2 * dpp + 3], aH, vlB + 2);
            }
        }

        __syncthreads();
        if (i + 2 < nkt) {
            load_kv(kb, pKh, pKl, pVh, pVl, pKs, i + 2, t);
            CP_COMMIT();
        }
    }

    // ---- finalize: normalize, split to bf16 hi/lo, store (fused) ----
    l0 += __shfl_xor_sync(0xffffffffu, l0, 1);
    l0 += __shfl_xor_sync(0xffffffffu, l0, 2);
    l1 += __shfl_xor_sync(0xffffffffu, l1, 1);
    l1 += __shfl_xor_sync(0xffffffffu, l1, 2);
    float i0 = __fdividef(1.f, l0);
    float i1 = __fdividef(1.f, l1);

    uint32_t* oh = (uint32_t*)g_atthi;
    uint32_t* ol = (uint32_t*)g_attlo;
    size_t base0 = (((size_t)(b * TSEQ + rg0)) * CDIM + h * HDIM + 2 * (lane & 3)) >> 1;
    size_t base1 = (((size_t)(b * TSEQ + rg1)) * CDIM + h * HDIM + 2 * (lane & 3)) >> 1;
#pragma unroll
    for (int dt = 0; dt < 8; dt++) {
        float v0 = O[dt][0] * i0, v1 = O[dt][1] * i0;
        float v2 = O[dt][2] * i1, v3 = O[dt][3] * i1;
        uint32_t h0 = pack_bf16x2(v1, v0);
        uint32_t h1 = pack_bf16x2(v3, v2);
        float r0 = v0 - __int_as_float(h0 << 16);
        float r1 = v1 - __int_as_float(h0 & 0xFFFF0000u);
        float r2 = v2 - __int_as_float(h1 << 16);
        float r3 = v3 - __int_as_float(h1 & 0xFFFF0000u);
        oh[base0 + dt * 4] = h0;
        ol[base0 + dt * 4] = pack_bf16x2(r1, r0);
        oh[base1 + dt * 4] = h1;
        ol[base1 + dt * 4] = pack_bf16x2(r3, r2);
    }
}

// ---------------------------------------------------------------------------
// Launch
// ---------------------------------------------------------------------------
extern "C" void kernel_launch(void* const* d_in, const int* in_sizes, int n_in,
                              void* d_out, int out_size) {
    const float* x     = (const float*)d_in[0];
    const float* w_qkv = (const float*)d_in[1];
    const float* b_qkv = (const float*)d_in[2];
    const float* w_out = (const float*)d_in[3];
    const float* b_out = (const float*)d_in[4];
    float* out = (float*)d_out;

    void *p_xhi, *p_xlo, *p_wqh, *p_wql, *p_woh, *p_wol, *p_ahi, *p_alo;
    cudaGetSymbolAddress(&p_xhi, g_xhi);
    cudaGetSymbolAddress(&p_xlo, g_xlo);
    cudaGetSymbolAddress(&p_wqh, g_wqkvT_hi);
    cudaGetSymbolAddress(&p_wql, g_wqkvT_lo);
    cudaGetSymbolAddress(&p_woh, g_woT_hi);
    cudaGetSymbolAddress(&p_wol, g_woT_lo);
    cudaGetSymbolAddress(&p_ahi, g_atthi);
    cudaGetSymbolAddress(&p_alo, g_attlo);

    static bool attr_done = false;
    if (!attr_done) {
        cudaFuncSetAttribute(mma_gemm_kernel,
                             cudaFuncAttributeMaxDynamicSharedMemorySize, GEMM_SMEM);
        cudaFuncSetAttribute(mma_gemm_qkv_kernel,
                             cudaFuncAttributeMaxDynamicSharedMemorySize, GEMM_SMEM);
        cudaFuncSetAttribute(yat_attn_mma,
                             cudaFuncAttributeMaxDynamicSharedMemorySize, ATT_SMEM);
        attr_done = true;
    }

    // 0) split x, transpose+split weights
    {
        int n4 = MTOT * KD / 4;
        split_kernel<<<(n4 + 255) / 256, 256>>>(x, (__nv_bfloat16*)p_xhi,
                                                (__nv_bfloat16*)p_xlo, n4);
        dim3 g1(N1 / 32, KD / 32);
        transpose_split_kernel<<<g1, 256>>>(w_qkv, (__nv_bfloat16*)p_wqh,
                                            (__nv_bfloat16*)p_wql, KD, N1);
        dim3 g2(CDIM / 32, KD / 32);
        transpose_split_kernel<<<g2, 256>>>(w_out, (__nv_bfloat16*)p_woh,
                                            (__nv_bfloat16*)p_wol, KD, CDIM);
    }

    // 1) QKV projection, fused epilogue -> per-head bf16 splits
    {
        dim3 grid(N1 / 128, MTOT / 128);
        mma_gemm_qkv_kernel<<<grid, 256, GEMM_SMEM>>>(
            (const __nv_bfloat16*)p_xhi, (const __nv_bfloat16*)p_xlo,
            (const __nv_bfloat16*)p_wqh, (const __nv_bfloat16*)p_wql, b_qkv);
    }

    // 2) sq-norms + HMMA flash attention (fused split epilogue)
    {
        dim3 gs((unsigned)(BHT / 8), 2);
        sqnorm_kernel<<<gs, 256>>>();
        dim3 grid(TSEQ / 128, NHEAD, BSZ);
        yat_attn_mma<<<grid, 256, ATT_SMEM>>>();
    }

    // 3) output projection
    {
        dim3 grid(CDIM / 128, MTOT / 128);
        mma_gemm_kernel<<<grid, 256, GEMM_SMEM>>>(
            (const __nv_bfloat16*)p_ahi, (const __nv_bfloat16*)p_alo,
            (const __nv_bfloat16*)p_woh, (const __nv_bfloat16*)p_wol,
            b_out, out, CDIM);
    }
}